// round 1
// baseline (speedup 1.0000x reference)
#include <cuda_runtime.h>
#include <cstdint>

#define KNN 64

// Lexicographic "greater" on (dist, idx): used for the max-heap so the worst
// kept neighbor (largest dist, then largest idx) sits at the root.
__device__ __forceinline__ bool key_greater(float d1, int i1, float d2, int i2) {
    return (d1 > d2) || (d1 == d2 && i1 > i2);
}

__device__ __forceinline__ void sift_down(float* hd, int* hidx, int start, int n) {
    int root = start;
    float rd = hd[root];
    int ri = hidx[root];
    while (true) {
        int child = 2 * root + 1;
        if (child >= n) break;
        float cd = hd[child];
        int ci = hidx[child];
        int child2 = child + 1;
        if (child2 < n) {
            float cd2 = hd[child2];
            int ci2 = hidx[child2];
            if (key_greater(cd2, ci2, cd, ci)) { child = child2; cd = cd2; ci = ci2; }
        }
        if (key_greater(cd, ci, rd, ri)) {
            hd[root] = cd; hidx[root] = ci;
            root = child;
        } else {
            break;
        }
    }
    hd[root] = rd;
    hidx[root] = ri;
}

extern __shared__ unsigned char smem_raw[];

__global__ void __launch_bounds__(256)
knn_kernel(const float4* __restrict__ coords,
           float* __restrict__ out_idx,
           float* __restrict__ out_dist,
           int S)
{
    float4* pts = reinterpret_cast<float4*>(smem_raw);
    float* sq   = reinterpret_cast<float*>(smem_raw + (size_t)S * sizeof(float4));

    const int blocksPerSeg = S / blockDim.x;
    const int seg = blockIdx.x / blocksPerSeg;
    const int q_local = (blockIdx.x % blocksPerSeg) * blockDim.x + threadIdx.x;

    // Stage the whole segment into SMEM, precompute |c|^2.
    const float4* segc = coords + (size_t)seg * S;
    for (int j = threadIdx.x; j < S; j += blockDim.x) {
        float4 c = segc[j];
        pts[j] = c;
        sq[j] = fmaf(c.x, c.x, fmaf(c.y, c.y, fmaf(c.z, c.z, c.w * c.w)));
    }
    __syncthreads();

    const float4 q = pts[q_local];
    const float sqi = sq[q_local];

    float hd[KNN];
    int hidx[KNN];

    // Seed with the first KNN candidates.
#pragma unroll
    for (int j = 0; j < KNN; j++) {
        float4 c = pts[j];
        float dot = fmaf(q.x, c.x, fmaf(q.y, c.y, fmaf(q.z, c.z, q.w * c.w)));
        hd[j] = sqi + sq[j] - 2.0f * dot;
        hidx[j] = j;
    }
    // Heapify.
    for (int s = KNN / 2 - 1; s >= 0; s--) sift_down(hd, hidx, s, KNN);

    float rootd = hd[0];

    // Scan remaining candidates. Indices arrive in increasing order, so any
    // tie with the root has a LARGER index than the root's -> strict < is the
    // exact lexicographic acceptance test.
#pragma unroll 4
    for (int j = KNN; j < S; j++) {
        float4 c = pts[j];
        float dot = fmaf(q.x, c.x, fmaf(q.y, c.y, fmaf(q.z, c.z, q.w * c.w)));
        float d2 = sqi + sq[j] - 2.0f * dot;
        if (d2 < rootd) {
            hd[0] = d2;
            hidx[0] = j;
            sift_down(hd, hidx, 0, KNN);
            rootd = hd[0];
        }
    }

    // Heapsort -> ascending (dist, idx).
    for (int end = KNN - 1; end > 0; end--) {
        float td = hd[0]; int ti = hidx[0];
        hd[0] = hd[end]; hidx[0] = hidx[end];
        hd[end] = td; hidx[end] = ti;
        sift_down(hd, hidx, 0, end);
    }

    const int gbase = seg * S;                    // global index offset
    const size_t obase = ((size_t)gbase + q_local) * KNN;
#pragma unroll
    for (int k = 0; k < KNN; k++) {
        out_idx[obase + k] = (float)(hidx[k] + gbase);
        if (out_dist) out_dist[obase + k] = fmaxf(hd[k], 0.0f);
    }
}

extern "C" void kernel_launch(void* const* d_in, const int* in_sizes, int n_in,
                              void* d_out, int out_size)
{
    // metadata order: K (scalar), coordinates [N*4 f32], row_splits [B+1 i32]
    const float4* coords = (const float4*)d_in[1];
    const int n_coord_floats = in_sizes[1];
    const int B = in_sizes[2] - 1;
    const int N = n_coord_floats / 4;   // D = 4
    const int S = N / B;                // equal-sized segments

    float* out = (float*)d_out;
    float* out_idx = out;
    // If the harness only holds one output, skip the dist write defensively.
    float* out_dist = ((long long)out_size >= 2LL * N * KNN) ? (out + (size_t)N * KNN)
                                                             : nullptr;

    size_t smem = (size_t)S * sizeof(float4) + (size_t)S * sizeof(float);
    cudaFuncSetAttribute(knn_kernel, cudaFuncAttributeMaxDynamicSharedMemorySize,
                         (int)smem);

    dim3 block(256);
    dim3 grid(N / 256);
    knn_kernel<<<grid, block, smem>>>(coords, out_idx, out_dist, S);
}

// round 2
// speedup vs baseline: 5.6452x; 5.6452x over previous
#include <cuda_runtime.h>
#include <cstdint>

#define KNN 64
#define RLIST 8
#define WARPS_PER_BLOCK 16
#define THREADS (WARPS_PER_BLOCK * 32)
#define FULLMASK 0xFFFFFFFFu

__global__ void __launch_bounds__(THREADS, 2)
knn_warp_kernel(const float4* __restrict__ coords,
                float* __restrict__ out_idx,
                float* __restrict__ out_dist,
                int S)
{
    extern __shared__ unsigned char smem_raw[];
    float4* pts = reinterpret_cast<float4*>(smem_raw);
    float* bufD = reinterpret_cast<float*>(smem_raw + (size_t)S * sizeof(float4));
    float* bufI = bufD + WARPS_PER_BLOCK * KNN;

    const int tid  = threadIdx.x;
    const int warp = tid >> 5;
    const int lane = tid & 31;

    // Block handles WARPS_PER_BLOCK consecutive queries, all in one segment.
    const int q_first   = blockIdx.x * WARPS_PER_BLOCK;     // global query id of warp 0
    const int seg       = q_first / S;
    const int q_local   = (q_first % S) + warp;             // this warp's query (segment-local)
    const int gbase     = seg * S;

    // ---- Stage the whole segment into SMEM ----
    const float4* segc = coords + (size_t)gbase;
    for (int i = tid; i < S; i += THREADS)
        pts[i] = segc[i];
    __syncthreads();

    const float4 q = pts[q_local];

    // ---- Per-lane top-RLIST selection over strided candidates ----
    float    L[RLIST];     // ascending distances
    unsigned I[RLIST];     // matching local indices
#pragma unroll
    for (int i = 0; i < RLIST; i++) { L[i] = __int_as_float(0x7F800000); I[i] = 0; }

    const int iters = S >> 5;       // candidates per lane
    for (int m = 0; m < iters; m++) {
        const int j = (m << 5) + lane;
        float4 c = pts[j];
        float dx = q.x - c.x, dy = q.y - c.y, dz = q.z - c.z, dw = q.w - c.w;
        float d2 = fmaf(dx, dx, fmaf(dy, dy, fmaf(dz, dz, dw * dw)));

        bool acc = d2 < L[RLIST - 1];
        if (__ballot_sync(FULLMASK, acc)) {
            // infinity-neutral branch-free sorted insert
            float    key  = acc ? d2 : __int_as_float(0x7F800000);
            unsigned kidx = (unsigned)j;
#pragma unroll
            for (int i = RLIST - 1; i >= 1; --i) {
                bool a = key < L[i - 1];
                bool b = key < L[i];
                float    nL = a ? L[i - 1] : (b ? key  : L[i]);
                unsigned nI = a ? I[i - 1] : (b ? kidx : I[i]);
                L[i] = nL; I[i] = nI;
            }
            if (key < L[0]) { I[0] = kidx; L[0] = key; }
        }
    }

    // ---- Warp tournament: emit the 64 smallest (dist, idx) in order ----
    float* wbD = bufD + warp * KNN;
    float* wbI = bufI + warp * KNN;
    unsigned pops = 0;

#pragma unroll 1
    for (int k = 0; k < KNN; ++k) {
        unsigned hb = __float_as_uint(L[0]);                 // nonneg float -> monotone bits
        unsigned mh = __reduce_min_sync(FULLMASK, hb);
        bool     m  = (hb == mh);
        unsigned il = m ? I[0] : 0xFFFFFFFFu;
        unsigned mi = __reduce_min_sync(FULLMASK, il);       // tie-break: lowest index
        bool     win = m && (I[0] == mi);
        if (win) { wbD[k] = L[0]; wbI[k] = (float)(gbase + (int)I[0]); }
        pops += win ? 1u : 0u;
        // branch-free pop-shift on the winning lane
#pragma unroll
        for (int i = 0; i < RLIST - 1; ++i) {
            L[i] = win ? L[i + 1] : L[i];
            I[i] = win ? I[i + 1] : I[i];
        }
        L[RLIST - 1] = win ? __int_as_float(0x7F800000) : L[RLIST - 1];
    }

    // ---- Exactness guard: if any lane contributed all RLIST slots, it may
    // have dropped a true neighbor. Rare (~0.8% of queries): exact rescan. ----
    bool unsafe = __ballot_sync(FULLMASK, pops >= RLIST) != 0;
    if (unsafe) {
        unsigned long long bound = 0ULL;
#pragma unroll 1
        for (int k = 0; k < KNN; ++k) {
            unsigned long long best = ~0ULL;
            for (int m2 = 0; m2 < iters; ++m2) {
                const int j = (m2 << 5) + lane;
                float4 c = pts[j];
                float dx = q.x - c.x, dy = q.y - c.y, dz = q.z - c.z, dw = q.w - c.w;
                float d2 = fmaf(dx, dx, fmaf(dy, dy, fmaf(dz, dz, dw * dw)));
                unsigned long long key =
                    ((unsigned long long)__float_as_uint(d2) << 32) | (unsigned)j;
                if (key >= bound && key < best) best = key;
            }
            unsigned hb = (unsigned)(best >> 32);
            unsigned mh = __reduce_min_sync(FULLMASK, hb);
            unsigned lo = (hb == mh) ? (unsigned)best : 0xFFFFFFFFu;
            unsigned ml = __reduce_min_sync(FULLMASK, lo);
            bool win = (hb == mh) && ((unsigned)best == ml);
            if (win) { wbD[k] = __uint_as_float(hb); wbI[k] = (float)(gbase + (int)ml); }
            bound = (((unsigned long long)mh << 32) | ml) + 1ULL;
        }
    }

    __syncwarp();

    // ---- Coalesced write-out ----
    const size_t ob = (size_t)(gbase + q_local) * KNN;
    out_idx [ob + lane]      = wbI[lane];
    out_idx [ob + lane + 32] = wbI[lane + 32];
    out_dist[ob + lane]      = wbD[lane];
    out_dist[ob + lane + 32] = wbD[lane + 32];
}

extern "C" void kernel_launch(void* const* d_in, const int* in_sizes, int n_in,
                              void* d_out, int out_size)
{
    // metadata order: K (scalar), coordinates [N*4 f32], row_splits [B+1 i32]
    const float4* coords = (const float4*)d_in[1];
    const int n_coord_floats = in_sizes[1];
    const int B = in_sizes[2] - 1;
    const int N = n_coord_floats / 4;   // D = 4
    const int S = N / B;                // equal-sized segments

    float* out = (float*)d_out;
    float* out_idx  = out;
    float* out_dist = out + (size_t)N * KNN;

    size_t smem = (size_t)S * sizeof(float4)
                + (size_t)WARPS_PER_BLOCK * KNN * 2 * sizeof(float);
    cudaFuncSetAttribute(knn_warp_kernel,
                         cudaFuncAttributeMaxDynamicSharedMemorySize, (int)smem);

    dim3 block(THREADS);
    dim3 grid(N / WARPS_PER_BLOCK);
    knn_warp_kernel<<<grid, block, smem>>>(coords, out_idx, out_dist, S);
}

// round 3
// speedup vs baseline: 10.2661x; 1.8186x over previous
#include <cuda_runtime.h>
#include <cstdint>

#define KNN 64
#define RL 10                 // per-lane top list
#define QPB 8                 // queries per block (2 warps each)
#define WPB 16
#define THREADS (WPB * 32)
#define POOLCAP 96
#define FULLMASK 0xFFFFFFFFu
#define FINF __int_as_float(0x7F800000)

__global__ void __launch_bounds__(THREADS, 2)
knn_pair_kernel(const float4* __restrict__ coords,
                float* __restrict__ out_idx,
                float* __restrict__ out_dist,
                int S)
{
    extern __shared__ unsigned char smem_raw[];
    float4* pts = reinterpret_cast<float4*>(smem_raw);
    unsigned long long* poolAll =
        reinterpret_cast<unsigned long long*>(smem_raw + (size_t)S * sizeof(float4));

    const int tid  = threadIdx.x;
    const int warp = tid >> 5;
    const int lane = tid & 31;
    const int pairIdx = warp >> 1;     // query slot within block (0..QPB-1)
    const int half    = warp & 1;      // which half of candidates this warp scans

    const int bps = S / QPB;                       // blocks per segment
    const int seg = blockIdx.x / bps;
    const int q_local = (blockIdx.x % bps) * QPB + pairIdx;
    const int gbase = seg * S;

    unsigned long long* mypool = poolAll + warp * POOLCAP;

    // ---- stage segment into smem ----
    const float4* segc = coords + (size_t)gbase;
    for (int i = tid; i < S; i += THREADS)
        pts[i] = segc[i];
    __syncthreads();

    const float4 q = pts[q_local];
    const int base = (half << 5) + lane;   // candidate offset within 64-stride
    const int iters = S >> 6;              // candidates per lane (64)

    // ---- per-lane top-RL scan over this warp's half of the candidates ----
    float    L[RL];
    unsigned I[RL];
#pragma unroll
    for (int i = 0; i < RL; i++) { L[i] = FINF; I[i] = 0; }
    float ev = FINF;   // exact (RL+1)-th smallest of this lane's stream

#pragma unroll 2
    for (int m = 0; m < iters; m++) {
        const int j = (m << 6) + base;
        float4 c = pts[j];
        float dx = q.x - c.x, dy = q.y - c.y, dz = q.z - c.z, dw = q.w - c.w;
        float d2 = fmaf(dx, dx, fmaf(dy, dy, fmaf(dz, dz, dw * dw)));

        // exact 11th tracking: accepted -> old L[RL-1] evicted; rejected -> d2.
        ev = fminf(ev, fmaxf(d2, L[RL - 1]));

        bool acc = d2 < L[RL - 1];
        if (__ballot_sync(FULLMASK, acc)) {
            float    key  = acc ? d2 : FINF;
            unsigned kidx = (unsigned)j;
#pragma unroll
            for (int i = RL - 1; i >= 1; --i) {
                bool a = key < L[i - 1];
                bool b = key < L[i];
                float    nL = a ? L[i - 1] : (b ? key  : L[i]);
                unsigned nI = a ? I[i - 1] : (b ? kidx : I[i]);
                L[i] = nL; I[i] = nI;
            }
            if (key < L[0]) { I[0] = kidx; L[0] = key; }
        }
    }

    // ---- binary search tau = 64th smallest over the warp's 32*RL values ----
    unsigned lb[RL];
#pragma unroll
    for (int i = 0; i < RL; i++) lb[i] = __float_as_uint(L[i]);

    unsigned lo = __reduce_min_sync(FULLMASK, lb[1]);      // count(<lo) <= 32 < 64
    unsigned hi = __reduce_max_sync(FULLMASK, lb[1]) + 1;  // count(<hi) >= 64
    while (lo + 1u < hi) {
        unsigned mid = lo + ((hi - lo) >> 1);
        unsigned cnt = 0;
#pragma unroll
        for (int i = 0; i < RL; i++) cnt += (lb[i] < mid) ? 1u : 0u;
        cnt = __reduce_add_sync(FULLMASK, cnt);
        if (cnt >= (unsigned)KNN) hi = mid; else lo = mid;
    }
    const unsigned tau = hi;

    // ---- collect qualifying elements (a sorted-prefix of each lane list) ----
    unsigned myq = 0;
#pragma unroll
    for (int i = 0; i < RL; i++) myq += (lb[i] < tau) ? 1u : 0u;

    // warp exclusive scan of myq
    unsigned inc = myq;
#pragma unroll
    for (int d = 1; d < 32; d <<= 1) {
        unsigned t = __shfl_up_sync(FULLMASK, inc, d);
        if (lane >= d) inc += t;
    }
    const unsigned pos = inc - myq;
    const unsigned c   = __shfl_sync(FULLMASK, inc, 31);

    bool deficient = (__ballot_sync(FULLMASK, __float_as_uint(ev) < tau) != 0)
                   || (c > POOLCAP);

    if (!deficient) {
        // write qualifying (lb[0..myq-1], ascending) into pool
        for (unsigned i = 0; i < myq; i++)
            mypool[pos + i] = (((unsigned long long)lb[i]) << 32) | I[i];
        __syncwarp();

        // rank sort in place (keys are distinct: unique local idx in low bits)
        unsigned long long key[3];
        int rnk[3];
#pragma unroll
        for (int r = 0; r < 3; r++) {
            int e = lane + 32 * r;
            key[r] = (e < (int)c) ? mypool[e] : ~0ULL;
            rnk[r] = 0;
        }
        for (int j = 0; j < (int)c; j++) {
            unsigned long long kj = mypool[j];
#pragma unroll
            for (int r = 0; r < 3; r++) rnk[r] += (kj < key[r]) ? 1 : 0;
        }
        __syncwarp();
#pragma unroll
        for (int r = 0; r < 3; r++) {
            int e = lane + 32 * r;
            if (e < (int)c) mypool[rnk[r]] = key[r];
        }
        __syncwarp();
    } else {
        // exact bound-tournament over this warp's 2048 candidates (rare)
        unsigned long long bound = 0ULL;
#pragma unroll 1
        for (int k = 0; k < KNN; k++) {
            unsigned long long best = ~0ULL;
            for (int m = 0; m < iters; m++) {
                const int j = (m << 6) + base;
                float4 cc = pts[j];
                float dx = q.x - cc.x, dy = q.y - cc.y,
                      dz = q.z - cc.z, dw = q.w - cc.w;
                float d2 = fmaf(dx, dx, fmaf(dy, dy, fmaf(dz, dz, dw * dw)));
                unsigned long long kk =
                    (((unsigned long long)__float_as_uint(d2)) << 32) | (unsigned)j;
                if (kk >= bound && kk < best) best = kk;
            }
            unsigned hb = (unsigned)(best >> 32);
            unsigned mh = __reduce_min_sync(FULLMASK, hb);
            unsigned lp = (hb == mh) ? (unsigned)best : 0xFFFFFFFFu;
            unsigned ml = __reduce_min_sync(FULLMASK, lp);
            if (lane == 0)
                mypool[k] = (((unsigned long long)mh) << 32) | ml;
            bound = ((((unsigned long long)mh) << 32) | ml) + 1ULL;
        }
        __syncwarp();
    }

    __syncthreads();

    // ---- merge the two sorted-64 lists of this query (half==0 warp only) ----
    if (half == 0) {
        const unsigned long long* A = mypool;
        const unsigned long long* B = mypool + POOLCAP;
        const size_t obase = (size_t)(gbase + q_local) * KNN;

#pragma unroll
        for (int t = 0; t < 2; t++) {
            const int r = lane + 32 * t;
            int alo = r - 63; if (alo < 0) alo = 0;
            int ahi = r + 1;  if (ahi > 64) ahi = 64;
            while (alo < ahi) {
                int a = (alo + ahi) >> 1;
                if (A[a] < B[r - a]) alo = a + 1; else ahi = a;
            }
            const int a = alo;
            unsigned long long va = (a > 0)      ? A[a - 1] : 0ULL;
            unsigned long long vb = (r - a >= 0) ? B[r - a] : 0ULL;
            unsigned long long res = (va > vb) ? va : vb;

            out_idx [obase + r] = (float)((int)(unsigned)res + gbase);
            out_dist[obase + r] = __uint_as_float((unsigned)(res >> 32));
        }
    }
}

extern "C" void kernel_launch(void* const* d_in, const int* in_sizes, int n_in,
                              void* d_out, int out_size)
{
    // metadata order: K (scalar), coordinates [N*4 f32], row_splits [B+1 i32]
    const float4* coords = (const float4*)d_in[1];
    const int n_coord_floats = in_sizes[1];
    const int B = in_sizes[2] - 1;
    const int N = n_coord_floats / 4;   // D = 4
    const int S = N / B;                // equal-sized segments (4096)

    float* out = (float*)d_out;
    float* out_idx  = out;
    float* out_dist = out + (size_t)N * KNN;

    size_t smem = (size_t)S * sizeof(float4)
                + (size_t)WPB * POOLCAP * sizeof(unsigned long long);

    cudaFuncSetAttribute(knn_pair_kernel,
                         cudaFuncAttributeMaxDynamicSharedMemorySize, (int)smem);
    // critical: allow 2 blocks/SM worth of shared memory carveout
    cudaFuncSetAttribute(knn_pair_kernel,
                         cudaFuncAttributePreferredSharedMemoryCarveout, 100);

    dim3 block(THREADS);
    dim3 grid(N / QPB);
    knn_pair_kernel<<<grid, block, smem>>>(coords, out_idx, out_dist, S);
}

// round 4
// speedup vs baseline: 17.7444x; 1.7284x over previous
#include <cuda_runtime.h>
#include <cstdint>

#define KNN 64
#define QPB 8                    // queries per block (2 warps each)
#define WPB 16
#define THREADS 512
#define POOLCAP 192
#define FULLMASK 0xFFFFFFFFu

__device__ __forceinline__ unsigned umax_(unsigned a, unsigned b) { return a > b ? a : b; }
__device__ __forceinline__ unsigned umin_(unsigned a, unsigned b) { return a < b ? a : b; }

template <int R>
__device__ __forceinline__ void rank_sort(const unsigned long long* pool, int c,
                                          unsigned long long* sorted, int lane)
{
    unsigned long long k[R];
    int r[R];
#pragma unroll
    for (int i = 0; i < R; i++) {
        int e = lane + 32 * i;
        k[i] = (e < c) ? pool[e] : ~0ULL;
        r[i] = 0;
    }
    for (int j = 0; j < c; j++) {
        unsigned long long kj = pool[j];        // broadcast LDS
#pragma unroll
        for (int i = 0; i < R; i++) r[i] += (kj < k[i]) ? 1 : 0;
    }
    __syncwarp();
#pragma unroll
    for (int i = 0; i < R; i++) {
        int e = lane + 32 * i;
        if (e < c && r[i] < KNN) sorted[r[i]] = k[i];
    }
}

__global__ void __launch_bounds__(THREADS, 2)
knn_2pass_kernel(const float4* __restrict__ coords,
                 float* __restrict__ out_idx,
                 float* __restrict__ out_dist,
                 int S)
{
    extern __shared__ unsigned char smem_raw[];
    float4* pts = reinterpret_cast<float4*>(smem_raw);
    unsigned long long* poolAll =
        reinterpret_cast<unsigned long long*>(smem_raw + (size_t)S * sizeof(float4));
    unsigned long long* sortedAll = poolAll + WPB * POOLCAP;

    const int tid  = threadIdx.x;
    const int warp = tid >> 5;
    const int lane = tid & 31;
    const int pairIdx = warp >> 1;   // query slot in block
    const int half    = warp & 1;    // which half of candidates this warp scans

    const int bps = S / QPB;
    const int seg = blockIdx.x / bps;
    const int q_local = (blockIdx.x % bps) * QPB + pairIdx;
    const int gbase = seg * S;

    // ---- stage segment ----
    const float4* segc = coords + (size_t)gbase;
    for (int i = tid; i < S; i += THREADS) pts[i] = segc[i];
    __syncthreads();

    const float4 q = pts[q_local];
    const int base  = (half << 5) + lane;
    const int iters = S >> 6;            // 64 candidates per lane

    // ---- pass 1: per-lane 3 smallest d2 bit-patterns (branch-free min/max) ----
    unsigned B0 = 0xFFFFFFFFu, B1 = 0xFFFFFFFFu, B2 = 0xFFFFFFFFu;
#pragma unroll 4
    for (int m = 0; m < iters; m++) {
        float4 c = pts[(m << 6) + base];
        float dx = q.x - c.x, dy = q.y - c.y, dz = q.z - c.z, dw = q.w - c.w;
        float d2 = fmaf(dx, dx, fmaf(dy, dy, fmaf(dz, dz, dw * dw)));
        unsigned db = __float_as_uint(d2);       // d2 >= 0 -> bits are order-monotone
        unsigned t2 = umax_(db, B1);
        unsigned t1 = umax_(db, B0);
        B2 = umin_(B2, t2);
        B1 = umin_(B1, t1);
        B0 = umin_(B0, db);
    }

    // ---- tau = (64th smallest of warp's 96 values) + 1, by bit binary search.
    //      Guaranteed upper bound on the warp's true 64th-smallest d2. ----
    unsigned lo = __reduce_min_sync(FULLMASK, B1);      // count(<lo) <= 32
    unsigned hi = __reduce_max_sync(FULLMASK, B2) + 1u; // count(<hi) == 96
    while (lo + 1u < hi) {
        unsigned mid = lo + ((hi - lo) >> 1);
        unsigned c96 = (unsigned)(B0 < mid) + (unsigned)(B1 < mid) + (unsigned)(B2 < mid);
        c96 = __reduce_add_sync(FULLMASK, c96);
        if (c96 >= 64u) hi = mid; else lo = mid;
    }
    const unsigned tau = hi;

    // ---- pass 2: collect every candidate with d2bits < tau into the pool ----
    unsigned long long* pool = poolAll + warp * POOLCAP;
    const unsigned ltm = (1u << lane) - 1u;
    unsigned cnt = 0;
#pragma unroll 4
    for (int m = 0; m < iters; m++) {
        const int j = (m << 6) + base;
        float4 c = pts[j];
        float dx = q.x - c.x, dy = q.y - c.y, dz = q.z - c.z, dw = q.w - c.w;
        float d2 = fmaf(dx, dx, fmaf(dy, dy, fmaf(dz, dz, dw * dw)));
        unsigned db = __float_as_uint(d2);
        bool acc = db < tau;
        unsigned ball = __ballot_sync(FULLMASK, acc);
        unsigned pos = cnt + __popc(ball & ltm);
        if (acc && pos < POOLCAP)
            pool[pos] = (((unsigned long long)db) << 32) | (unsigned)j;
        cnt += __popc(ball);
    }
    __syncwarp();

    unsigned long long* sorted = sortedAll + warp * KNN;

    if (cnt <= 96u) {
        rank_sort<3>(pool, (int)cnt, sorted, lane);
    } else if (cnt <= (unsigned)POOLCAP) {
        rank_sort<6>(pool, (int)cnt, sorted, lane);
    } else {
        // pool overflow (essentially impossible for this data): exact
        // bound-tournament over this warp's candidates.
        unsigned long long bound = 0ULL;
#pragma unroll 1
        for (int k = 0; k < KNN; k++) {
            unsigned long long best = ~0ULL;
            for (int m = 0; m < iters; m++) {
                const int j = (m << 6) + base;
                float4 c = pts[j];
                float dx = q.x - c.x, dy = q.y - c.y, dz = q.z - c.z, dw = q.w - c.w;
                float d2 = fmaf(dx, dx, fmaf(dy, dy, fmaf(dz, dz, dw * dw)));
                unsigned long long kk =
                    (((unsigned long long)__float_as_uint(d2)) << 32) | (unsigned)j;
                if (kk >= bound && kk < best) best = kk;
            }
            unsigned hb = (unsigned)(best >> 32);
            unsigned mh = __reduce_min_sync(FULLMASK, hb);
            unsigned lb = (hb == mh) ? (unsigned)best : 0xFFFFFFFFu;
            unsigned ml = __reduce_min_sync(FULLMASK, lb);
            if (lane == 0) sorted[k] = (((unsigned long long)mh) << 32) | ml;
            bound = ((((unsigned long long)mh) << 32) | ml) + 1ULL;
        }
        __syncwarp();
    }

    __syncthreads();

    // ---- merge-path join of the two sorted-64 lists; write output ----
    if (half == 0) {
        const unsigned long long* A = sortedAll + warp * KNN;  // this warp (half 0)
        const unsigned long long* B = A + KNN;                  // partner (half 1)
        const size_t obase = (size_t)(gbase + q_local) * KNN;

#pragma unroll
        for (int t = 0; t < 2; t++) {
            const int r = lane + 32 * t;
            int alo = r - 63; if (alo < 0) alo = 0;
            int ahi = r + 1;  if (ahi > 64) ahi = 64;
            while (alo < ahi) {
                int a = (alo + ahi) >> 1;
                if (A[a] < B[r - a]) alo = a + 1; else ahi = a;
            }
            const int a = alo;
            unsigned long long va = (a > 0)      ? A[a - 1] : 0ULL;
            unsigned long long vb = (r - a >= 0) ? B[r - a] : 0ULL;
            unsigned long long res = (va > vb) ? va : vb;

            out_idx [obase + r] = (float)((int)(unsigned)res + gbase);
            out_dist[obase + r] = __uint_as_float((unsigned)(res >> 32));
        }
    }
}

extern "C" void kernel_launch(void* const* d_in, const int* in_sizes, int n_in,
                              void* d_out, int out_size)
{
    // metadata order: K (scalar), coordinates [N*4 f32], row_splits [B+1 i32]
    const float4* coords = (const float4*)d_in[1];
    const int n_coord_floats = in_sizes[1];
    const int B = in_sizes[2] - 1;
    const int N = n_coord_floats / 4;   // D = 4
    const int S = N / B;                // equal-sized segments (4096)

    float* out = (float*)d_out;
    float* out_idx  = out;
    float* out_dist = out + (size_t)N * KNN;

    size_t smem = (size_t)S * sizeof(float4)
                + (size_t)WPB * POOLCAP * sizeof(unsigned long long)
                + (size_t)WPB * KNN * sizeof(unsigned long long);

    cudaFuncSetAttribute(knn_2pass_kernel,
                         cudaFuncAttributeMaxDynamicSharedMemorySize, (int)smem);
    cudaFuncSetAttribute(knn_2pass_kernel,
                         cudaFuncAttributePreferredSharedMemoryCarveout, 100);

    dim3 block(THREADS);
    dim3 grid(N / QPB);
    knn_2pass_kernel<<<grid, block, smem>>>(coords, out_idx, out_dist, S);
}

// round 5
// speedup vs baseline: 21.5622x; 1.2152x over previous
#include <cuda_runtime.h>
#include <cstdint>

#define KNN 64
#define QPB 8                    // queries per block (2 warps each)
#define WPB 16
#define THREADS 512
#define POOLCAP 128
#define FULLMASK 0xFFFFFFFFu

__device__ __forceinline__ unsigned umax_(unsigned a, unsigned b) { return a > b ? a : b; }
__device__ __forceinline__ unsigned umin_(unsigned a, unsigned b) { return a < b ? a : b; }

// Rank-sort c pool entries (exact u64 keys, all distinct) into sorted[0..63].
template <int R>
__device__ __forceinline__ void rank_sort(const unsigned long long* pool, int c,
                                          unsigned long long* sorted, int lane)
{
    unsigned long long k[R];
    int r[R];
#pragma unroll
    for (int i = 0; i < R; i++) {
        int e = lane + 32 * i;
        k[i] = (e < c) ? pool[e] : ~0ULL;
        r[i] = 0;
    }
    for (int j = 0; j < c; j++) {
        unsigned long long kj = pool[j];        // broadcast LDS
#pragma unroll
        for (int i = 0; i < R; i++) r[i] += (kj < k[i]) ? 1 : 0;
    }
    __syncwarp();
#pragma unroll
    for (int i = 0; i < R; i++) {
        int e = lane + 32 * i;
        if (e < c && r[i] < KNN) sorted[r[i]] = k[i];
    }
}

__global__ void __launch_bounds__(THREADS, 2)
knn_sharedtau_kernel(const float4* __restrict__ coords,
                     float* __restrict__ out_idx,
                     float* __restrict__ out_dist,
                     int S)
{
    extern __shared__ unsigned char smem_raw[];
    float4* pts = reinterpret_cast<float4*>(smem_raw);
    size_t off = (size_t)S * sizeof(float4);
    unsigned* exch = reinterpret_cast<unsigned*>(smem_raw + off);          // WPB*64 u32
    off += (size_t)WPB * 64 * sizeof(unsigned);
    unsigned long long* poolAll = reinterpret_cast<unsigned long long*>(smem_raw + off);
    off += (size_t)WPB * POOLCAP * sizeof(unsigned long long);
    unsigned long long* sortedAll = reinterpret_cast<unsigned long long*>(smem_raw + off);
    off += (size_t)WPB * KNN * sizeof(unsigned long long);
    int* warpCnt = reinterpret_cast<int*>(smem_raw + off);                 // WPB ints

    const int tid  = threadIdx.x;
    const int warp = tid >> 5;
    const int lane = tid & 31;
    const int pairIdx = warp >> 1;   // query slot in block
    const int half    = warp & 1;    // which half of candidates this warp scans

    const int bps = S / QPB;
    const int seg = blockIdx.x / bps;
    const int q_local = (blockIdx.x % bps) * QPB + pairIdx;
    const int gbase = seg * S;

    // ---- stage segment ----
    const float4* segc = coords + (size_t)gbase;
    for (int i = tid; i < S; i += THREADS) pts[i] = segc[i];
    if (lane == 0) warpCnt[warp] = 0;
    __syncthreads();

    const float4 q = pts[q_local];
    const int base  = (half << 5) + lane;
    const int iters = S >> 6;            // 64 candidates per lane

    // ---- pass 1: per-lane 2 smallest d2 bit-patterns (3 IMNMX / candidate) ----
    unsigned B0 = 0xFFFFFFFFu, B1 = 0xFFFFFFFFu;
#pragma unroll 4
    for (int m = 0; m < iters; m++) {
        float4 c = pts[(m << 6) + base];
        float dx = q.x - c.x, dy = q.y - c.y, dz = q.z - c.z, dw = q.w - c.w;
        float d2 = fmaf(dx, dx, fmaf(dy, dy, fmaf(dz, dz, dw * dw)));
        unsigned db = __float_as_uint(d2);       // d2 >= 0 -> bits order-monotone
        unsigned t1 = umax_(db, B0);
        B1 = umin_(B1, t1);
        B0 = umin_(B0, db);
    }

    // ---- exchange top-2s with partner warp; compute COMBINED tau for the query:
    //      tau = (64th smallest of the 128 collected values) + 1  >= true 64th+1 ----
    exch[warp * 64 + lane * 2]     = B0;
    exch[warp * 64 + lane * 2 + 1] = B1;
    __syncthreads();
    const unsigned p0 = exch[(warp ^ 1) * 64 + lane * 2];
    const unsigned p1 = exch[(warp ^ 1) * 64 + lane * 2 + 1];

    unsigned lo = __reduce_min_sync(FULLMASK, umin_(B0, p0));       // count(<lo)=0
    unsigned hi = __reduce_max_sync(FULLMASK, umax_(B1, p1)) + 1u;  // count(<hi)=128
    while (lo + 1u < hi) {
        unsigned mid = lo + ((hi - lo) >> 1);
        unsigned c4 = (unsigned)(B0 < mid) + (unsigned)(B1 < mid)
                    + (unsigned)(p0 < mid) + (unsigned)(p1 < mid);
        c4 = __reduce_add_sync(FULLMASK, c4);
        if (c4 >= 64u) hi = mid; else lo = mid;
    }
    const unsigned tau = hi;   // identical across the warp pair (same 128 inputs)

    // ---- pass 2: collect this half's candidates with db < tau (atomic append;
    //      pool order is irrelevant — the exact u64 sort canonicalizes) ----
    unsigned long long* pool = poolAll + warp * POOLCAP;
#pragma unroll 4
    for (int m = 0; m < iters; m++) {
        const int j = (m << 6) + base;
        float4 c = pts[j];
        float dx = q.x - c.x, dy = q.y - c.y, dz = q.z - c.z, dw = q.w - c.w;
        float d2 = fmaf(dx, dx, fmaf(dy, dy, fmaf(dz, dz, dw * dw)));
        unsigned db = __float_as_uint(d2);
        if (db < tau) {
            int pos = atomicAdd(&warpCnt[warp], 1);
            if (pos < POOLCAP)
                pool[pos] = (((unsigned long long)db) << 32) | (unsigned)j;
        }
    }
    __syncwarp();
    const int cnt = warpCnt[warp];

    // ---- pad + sort this warp's pool into sorted[0..63] ----
    unsigned long long* sorted = sortedAll + warp * KNN;
    sorted[lane]      = ~0ULL;
    sorted[lane + 32] = ~0ULL;
    __syncwarp();

    if (cnt <= 64) {
        rank_sort<2>(pool, cnt, sorted, lane);
    } else if (cnt <= POOLCAP) {
        rank_sort<4>(pool, cnt, sorted, lane);
    } else {
        // pool overflow (pathological): exact bound-tournament over this half.
        unsigned long long bound = 0ULL;
#pragma unroll 1
        for (int k = 0; k < KNN; k++) {
            unsigned long long best = ~0ULL;
            for (int m = 0; m < iters; m++) {
                const int j = (m << 6) + base;
                float4 c = pts[j];
                float dx = q.x - c.x, dy = q.y - c.y, dz = q.z - c.z, dw = q.w - c.w;
                float d2 = fmaf(dx, dx, fmaf(dy, dy, fmaf(dz, dz, dw * dw)));
                unsigned long long kk =
                    (((unsigned long long)__float_as_uint(d2)) << 32) | (unsigned)j;
                if (kk >= bound && kk < best) best = kk;
            }
            unsigned hb = (unsigned)(best >> 32);
            unsigned mh = __reduce_min_sync(FULLMASK, hb);
            unsigned lb = (hb == mh) ? (unsigned)best : 0xFFFFFFFFu;
            unsigned ml = __reduce_min_sync(FULLMASK, lb);
            if (lane == 0) sorted[k] = (((unsigned long long)mh) << 32) | ml;
            bound = ((((unsigned long long)mh) << 32) | ml) + 1ULL;
        }
        __syncwarp();
    }

    __syncthreads();

    // ---- merge-path join of the two sorted-64 lists; write output ----
    if (half == 0) {
        const unsigned long long* A = sortedAll + warp * KNN;   // this warp
        const unsigned long long* B = A + KNN;                  // partner
        const size_t obase = (size_t)(gbase + q_local) * KNN;

#pragma unroll
        for (int t = 0; t < 2; t++) {
            const int r = lane + 32 * t;
            int alo = r - 63; if (alo < 0) alo = 0;
            int ahi = r + 1;  if (ahi > 64) ahi = 64;
            while (alo < ahi) {
                int a = (alo + ahi) >> 1;
                if (A[a] < B[r - a]) alo = a + 1; else ahi = a;
            }
            const int a = alo;
            unsigned long long va = (a > 0)      ? A[a - 1] : 0ULL;
            unsigned long long vb = (r - a >= 0) ? B[r - a] : 0ULL;
            unsigned long long res = (va > vb) ? va : vb;

            out_idx [obase + r] = (float)((int)(unsigned)res + gbase);
            out_dist[obase + r] = __uint_as_float((unsigned)(res >> 32));
        }
    }
}

extern "C" void kernel_launch(void* const* d_in, const int* in_sizes, int n_in,
                              void* d_out, int out_size)
{
    // metadata order: K (scalar), coordinates [N*4 f32], row_splits [B+1 i32]
    const float4* coords = (const float4*)d_in[1];
    const int n_coord_floats = in_sizes[1];
    const int B = in_sizes[2] - 1;
    const int N = n_coord_floats / 4;   // D = 4
    const int S = N / B;                // equal-sized segments (4096)

    float* out = (float*)d_out;
    float* out_idx  = out;
    float* out_dist = out + (size_t)N * KNN;

    size_t smem = (size_t)S * sizeof(float4)
                + (size_t)WPB * 64 * sizeof(unsigned)
                + (size_t)WPB * POOLCAP * sizeof(unsigned long long)
                + (size_t)WPB * KNN * sizeof(unsigned long long)
                + (size_t)WPB * sizeof(int);

    cudaFuncSetAttribute(knn_sharedtau_kernel,
                         cudaFuncAttributeMaxDynamicSharedMemorySize, (int)smem);
    cudaFuncSetAttribute(knn_sharedtau_kernel,
                         cudaFuncAttributePreferredSharedMemoryCarveout, 100);

    dim3 block(THREADS);
    dim3 grid(N / QPB);
    knn_sharedtau_kernel<<<grid, block, smem>>>(coords, out_idx, out_dist, S);
}